// round 13
// baseline (speedup 1.0000x reference)
#include <cuda_runtime.h>

#define B_TOT 2048
#define IN    256
#define INP1  257
#define OUT   256

#define THREADS 128
#define NWARP   4
#define OBLK    32          // o's per block: lane -> o
#define BW      8           // b's per warp
#define BBLK    32          // b's per block (= NWARP * BW)
#define CHUNK   32          // i's per stage
#define NCHUNK  (IN / CHUNK)

__global__ __launch_bounds__(THREADS) void skan_kernel(
    const float* __restrict__ x,       // [B_TOT, IN]
    const float* __restrict__ weight,  // [OUT, INP1]
    const float* __restrict__ w,       // [OUT, INP1]
    float* __restrict__ out)           // [B_TOT, OUT]
{
    // Interleaved (w, weight) pairs: wp[buf][i][o]. Row padded to 33 float2 so
    // both the transposed STS (lane -> i) and the per-lane LDS.64 (lane -> o)
    // are bank-conflict-free.
    __shared__ float2 wpair[2][CHUNK][OBLK + 1];
    // x chunk, row-major [b][i]: STS lanes write consecutive i (conflict-free),
    // reads are warp-uniform broadcast float4 (16B-aligned: b*128B + i*4B).
    __shared__ float xs[2][BBLK][CHUNK];

    const int tid    = threadIdx.x;
    const int lane   = tid & 31;
    const int wid    = tid >> 5;
    const int o_base = blockIdx.y * OBLK;
    const int o      = o_base + lane;
    const int b_base = blockIdx.x * BBLK;

    // Bias column (x_ext[:,256] == 1): constant per o -> fold into init.
    float acc[BW];
    {
        float wb  = w[(size_t)o * INP1 + IN];
        float wtb = weight[(size_t)o * INP1 + IN];
        float bi  = wtb * __sinf(wb);
#pragma unroll
        for (int b = 0; b < BW; ++b) acc[b] = bi;
    }

    // Register prefetch: weights 32 o-rows x 32 i / 128 thr = 8/thread each;
    // x 32 b-rows x 32 i / 128 thr = 8/thread.
    float pw[8], pwt[8], px[8];

#pragma unroll
    for (int p = 0; p < 8; ++p) {
        int r = p * NWARP + wid;
        pw [p] = w     [(size_t)(o_base + r) * INP1 + lane];
        pwt[p] = weight[(size_t)(o_base + r) * INP1 + lane];
        px [p] = x     [(size_t)(b_base + r) * IN   + lane];
    }

    for (int c = 0; c < NCHUNK; ++c) {
        const int buf = c & 1;

        // Stage prefetched chunk. wpair STS: addr=(lane*33+r) float2 ->
        // banks (2*lane + 2*r) mod 32, distinct within each 16-lane phase.
#pragma unroll
        for (int p = 0; p < 8; ++p) {
            int r = p * NWARP + wid;
            wpair[buf][lane][r] = make_float2(pw[p], pwt[p]);
            xs[buf][r][lane]    = px[p];
        }
        __syncthreads();

        // Kick off next chunk's LDGs; latency hides under compute.
        if (c + 1 < NCHUNK) {
            int ci = (c + 1) * CHUNK + lane;
#pragma unroll
            for (int p = 0; p < 8; ++p) {
                int r = p * NWARP + wid;
                pw [p] = w     [(size_t)(o_base + r) * INP1 + ci];
                pwt[p] = weight[(size_t)(o_base + r) * INP1 + ci];
                px [p] = x     [(size_t)(b_base + r) * IN   + ci];
            }
        }

        // Compute: 4 i's per step. Weight pairs per-lane (reused over 8 b's),
        // x as one broadcast LDS.128 per b (serves all 32 lanes/o's).
#pragma unroll 2
        for (int i4 = 0; i4 < CHUNK / 4; ++i4) {
            float2 wp0 = wpair[buf][i4 * 4 + 0][lane];
            float2 wp1 = wpair[buf][i4 * 4 + 1][lane];
            float2 wp2 = wpair[buf][i4 * 4 + 2][lane];
            float2 wp3 = wpair[buf][i4 * 4 + 3][lane];
#pragma unroll
            for (int b = 0; b < BW; ++b) {
                float4 xv = *reinterpret_cast<const float4*>(
                    &xs[buf][wid * BW + b][i4 * 4]);
                acc[b] = fmaf(wp0.y, __sinf(wp0.x * xv.x), acc[b]);
                acc[b] = fmaf(wp1.y, __sinf(wp1.x * xv.y), acc[b]);
                acc[b] = fmaf(wp2.y, __sinf(wp2.x * xv.z), acc[b]);
                acc[b] = fmaf(wp3.y, __sinf(wp3.x * xv.w), acc[b]);
            }
        }
        // Buffer reuse (c+2) is fenced by the c+1 __syncthreads.
    }

    // Store: per b, warp writes 32 consecutive o's -> coalesced 128B STG.
#pragma unroll
    for (int b = 0; b < BW; ++b) {
        int bb = b_base + wid * BW + b;
        out[(size_t)bb * OUT + o] = acc[b];
    }
}

extern "C" void kernel_launch(void* const* d_in, const int* in_sizes, int n_in,
                              void* d_out, int out_size) {
    const float* x      = (const float*)d_in[0];
    const float* weight = (const float*)d_in[1];
    const float* w      = (const float*)d_in[2];
    float* out          = (float*)d_out;

    dim3 grid(B_TOT / BBLK, OUT / OBLK);  // (64, 8) = 512 CTAs, single wave
    skan_kernel<<<grid, THREADS>>>(x, weight, w, out);
}

// round 16
// speedup vs baseline: 1.0118x; 1.0118x over previous
#include <cuda_runtime.h>

#define B_TOT 2048
#define IN    256
#define INP1  257
#define OUT   256

#define THREADS 128
#define NWARP   4
#define OBLK    32          // o's per block: lane -> o
#define BW      8           // b's per warp
#define BBLK    32          // b's per block (= NWARP * BW)
#define CHUNK   32          // i's per stage
#define NCHUNK  (IN / CHUNK)

__global__ __launch_bounds__(THREADS) void skan_kernel(
    const float* __restrict__ x,       // [B_TOT, IN]
    const float* __restrict__ weight,  // [OUT, INP1]
    const float* __restrict__ w,       // [OUT, INP1]
    float* __restrict__ out)           // [B_TOT, OUT]
{
    // Interleaved (w, weight) pairs: wp[buf][i][o]. Row padded to 33 float2 so
    // both the transposed STS (lane -> i) and the per-lane LDS.64 (lane -> o)
    // are bank-conflict-free.
    __shared__ float2 wpair[2][CHUNK][OBLK + 1];
    // x chunk, row-major [b][i]: STS lanes write consecutive i (conflict-free),
    // reads are warp-uniform broadcast float4 (16B-aligned: b*128B + i*4B).
    __shared__ float xs[2][BBLK][CHUNK];

    const int tid    = threadIdx.x;
    const int lane   = tid & 31;
    const int wid    = tid >> 5;
    const int o_base = blockIdx.y * OBLK;
    const int o      = o_base + lane;
    const int b_base = blockIdx.x * BBLK;

    // Bias column (x_ext[:,256] == 1): constant per o -> fold into init.
    float acc[BW];
    {
        float wb  = w[(size_t)o * INP1 + IN];
        float wtb = weight[(size_t)o * INP1 + IN];
        float bi  = wtb * __sinf(wb);
#pragma unroll
        for (int b = 0; b < BW; ++b) acc[b] = bi;
    }

    // Register prefetch: weights 32 o-rows x 32 i / 128 thr = 8/thread each;
    // x 32 b-rows x 32 i / 128 thr = 8/thread.
    float pw[8], pwt[8], px[8];

#pragma unroll
    for (int p = 0; p < 8; ++p) {
        int r = p * NWARP + wid;
        pw [p] = w     [(size_t)(o_base + r) * INP1 + lane];
        pwt[p] = weight[(size_t)(o_base + r) * INP1 + lane];
        px [p] = x     [(size_t)(b_base + r) * IN   + lane];
    }

    for (int c = 0; c < NCHUNK; ++c) {
        const int buf = c & 1;

        // Stage prefetched chunk. wpair STS: addr=(lane*33+r) float2 ->
        // banks (2*lane + 2*r) mod 32, distinct within each 16-lane phase.
#pragma unroll
        for (int p = 0; p < 8; ++p) {
            int r = p * NWARP + wid;
            wpair[buf][lane][r] = make_float2(pw[p], pwt[p]);
            xs[buf][r][lane]    = px[p];
        }
        __syncthreads();

        // Kick off next chunk's LDGs; latency hides under compute.
        if (c + 1 < NCHUNK) {
            int ci = (c + 1) * CHUNK + lane;
#pragma unroll
            for (int p = 0; p < 8; ++p) {
                int r = p * NWARP + wid;
                pw [p] = w     [(size_t)(o_base + r) * INP1 + ci];
                pwt[p] = weight[(size_t)(o_base + r) * INP1 + ci];
                px [p] = x     [(size_t)(b_base + r) * IN   + ci];
            }
        }

        // Compute: 4 i's per step. Weight pairs per-lane (reused over 8 b's),
        // x as one broadcast LDS.128 per b (serves all 32 lanes/o's).
#pragma unroll 2
        for (int i4 = 0; i4 < CHUNK / 4; ++i4) {
            float2 wp0 = wpair[buf][i4 * 4 + 0][lane];
            float2 wp1 = wpair[buf][i4 * 4 + 1][lane];
            float2 wp2 = wpair[buf][i4 * 4 + 2][lane];
            float2 wp3 = wpair[buf][i4 * 4 + 3][lane];
#pragma unroll
            for (int b = 0; b < BW; ++b) {
                float4 xv = *reinterpret_cast<const float4*>(
                    &xs[buf][wid * BW + b][i4 * 4]);
                acc[b] = fmaf(wp0.y, __sinf(wp0.x * xv.x), acc[b]);
                acc[b] = fmaf(wp1.y, __sinf(wp1.x * xv.y), acc[b]);
                acc[b] = fmaf(wp2.y, __sinf(wp2.x * xv.z), acc[b]);
                acc[b] = fmaf(wp3.y, __sinf(wp3.x * xv.w), acc[b]);
            }
        }
        // Buffer reuse (c+2) is fenced by the c+1 __syncthreads.
    }

    // Store: per b, warp writes 32 consecutive o's -> coalesced 128B STG.
#pragma unroll
    for (int b = 0; b < BW; ++b) {
        int bb = b_base + wid * BW + b;
        out[(size_t)bb * OUT + o] = acc[b];
    }
}

extern "C" void kernel_launch(void* const* d_in, const int* in_sizes, int n_in,
                              void* d_out, int out_size) {
    const float* x      = (const float*)d_in[0];
    const float* weight = (const float*)d_in[1];
    const float* w      = (const float*)d_in[2];
    float* out          = (float*)d_out;

    dim3 grid(B_TOT / BBLK, OUT / OBLK);  // (64, 8) = 512 CTAs, single wave
    skan_kernel<<<grid, THREADS>>>(x, weight, w, out);
}

// round 17
// speedup vs baseline: 1.1781x; 1.1644x over previous
#include <cuda_runtime.h>

#define B_TOT 2048
#define IN    256
#define INP1  257
#define OUT   256

#define THREADS 128
#define NWARP   4
#define OBLK    32          // o's per block: lane -> o
#define BW      4           // b's per warp
#define BBLK    16          // b's per block (= NWARP * BW)
#define CHUNK   32          // i's per stage
#define NCHUNK  (IN / CHUNK)

__global__ __launch_bounds__(THREADS) void skan_kernel(
    const float* __restrict__ x,       // [B_TOT, IN]
    const float* __restrict__ weight,  // [OUT, INP1]
    const float* __restrict__ w,       // [OUT, INP1]
    float* __restrict__ out)           // [B_TOT, OUT]
{
    // Interleaved (w, weight) pairs: wpair[buf][i][o]. Row padded to 33
    // float2: transposed STS (lane -> i) and per-lane LDS.64 (lane -> o) are
    // both conflict-free (2-bank stride resolved in 16-lane phases).
    __shared__ float2 wpair[2][CHUNK][OBLK + 1];
    // x chunk row-major [b][i]: STS conflict-free, reads are warp-uniform
    // broadcast LDS.128 (16B-aligned: b*128B + i4*16B).
    __shared__ float xs[2][BBLK][CHUNK];

    const int tid    = threadIdx.x;
    const int lane   = tid & 31;
    const int wid    = tid >> 5;
    const int o_base = blockIdx.y * OBLK;
    const int o      = o_base + lane;
    const int b_base = blockIdx.x * BBLK;

    // Bias column (x_ext[:,256] == 1): constant per o -> fold into init.
    float acc[BW];
    {
        float wb  = w[(size_t)o * INP1 + IN];
        float wtb = weight[(size_t)o * INP1 + IN];
        float bi  = wtb * __sinf(wb);
#pragma unroll
        for (int b = 0; b < BW; ++b) acc[b] = bi;
    }

    // Register prefetch: weights 32 o-rows x 32 i / 128 thr = 8/thread each;
    // x 16 b-rows x 32 i / 128 thr = 4/thread.
    float pw[8], pwt[8], px[4];

#pragma unroll
    for (int p = 0; p < 8; ++p) {
        int r = p * NWARP + wid;
        pw [p] = w     [(size_t)(o_base + r) * INP1 + lane];
        pwt[p] = weight[(size_t)(o_base + r) * INP1 + lane];
    }
#pragma unroll
    for (int p = 0; p < BW; ++p) {
        int r = p * NWARP + wid;
        px[p] = x[(size_t)(b_base + r) * IN + lane];
    }

    for (int c = 0; c < NCHUNK; ++c) {
        const int buf = c & 1;

        // Stage prefetched chunk (weights transposed into [i][o]).
#pragma unroll
        for (int p = 0; p < 8; ++p) {
            int r = p * NWARP + wid;
            wpair[buf][lane][r] = make_float2(pw[p], pwt[p]);
        }
#pragma unroll
        for (int p = 0; p < BW; ++p) {
            int r = p * NWARP + wid;
            xs[buf][r][lane] = px[p];
        }
        __syncthreads();

        // Kick off next chunk's LDGs; latency hides under compute.
        if (c + 1 < NCHUNK) {
            int ci = (c + 1) * CHUNK + lane;
#pragma unroll
            for (int p = 0; p < 8; ++p) {
                int r = p * NWARP + wid;
                pw [p] = w     [(size_t)(o_base + r) * INP1 + ci];
                pwt[p] = weight[(size_t)(o_base + r) * INP1 + ci];
            }
#pragma unroll
            for (int p = 0; p < BW; ++p) {
                int r = p * NWARP + wid;
                px[p] = x[(size_t)(b_base + r) * IN + ci];
            }
        }

        // Compute: 4 i's per step. Weight pairs per-lane (reused over 4 b's),
        // x as one broadcast LDS.128 per b (serves all 32 lanes/o's).
#pragma unroll 2
        for (int i4 = 0; i4 < CHUNK / 4; ++i4) {
            float2 wp0 = wpair[buf][i4 * 4 + 0][lane];
            float2 wp1 = wpair[buf][i4 * 4 + 1][lane];
            float2 wp2 = wpair[buf][i4 * 4 + 2][lane];
            float2 wp3 = wpair[buf][i4 * 4 + 3][lane];
#pragma unroll
            for (int b = 0; b < BW; ++b) {
                float4 xv = *reinterpret_cast<const float4*>(
                    &xs[buf][wid * BW + b][i4 * 4]);
                acc[b] = fmaf(wp0.y, __sinf(wp0.x * xv.x), acc[b]);
                acc[b] = fmaf(wp1.y, __sinf(wp1.x * xv.y), acc[b]);
                acc[b] = fmaf(wp2.y, __sinf(wp2.x * xv.z), acc[b]);
                acc[b] = fmaf(wp3.y, __sinf(wp3.x * xv.w), acc[b]);
            }
        }
        // Buffer reuse (c+2) is fenced by the c+1 __syncthreads.
    }

    // Store: per b, warp writes 32 consecutive o's -> coalesced 128B STG.
#pragma unroll
    for (int b = 0; b < BW; ++b) {
        int bb = b_base + wid * BW + b;
        out[(size_t)bb * OUT + o] = acc[b];
    }
}

extern "C" void kernel_launch(void* const* d_in, const int* in_sizes, int n_in,
                              void* d_out, int out_size) {
    const float* x      = (const float*)d_in[0];
    const float* weight = (const float*)d_in[1];
    const float* w      = (const float*)d_in[2];
    float* out          = (float*)d_out;

    dim3 grid(B_TOT / BBLK, OUT / OBLK);  // (128, 8) = 1024 CTAs
    skan_kernel<<<grid, THREADS>>>(x, weight, w, out);
}